// round 1
// baseline (speedup 1.0000x reference)
#include <cuda_runtime.h>
#include <math.h>

// Problem constants
#define Bb 2
#define Nn 1024
#define Mm 1024
#define Cc 1024
#define Hh 16
#define Ss 8
#define Pp 4
#define HDd 64
#define SDd 8

// Scratch (device globals — no allocation allowed in kernel_launch)
__device__ float g_q[(size_t)Bb * Nn * Cc];     // weighted Q projection
__device__ float g_k[(size_t)Bb * Mm * Cc];
__device__ float g_v[(size_t)Bb * Mm * Cc];
__device__ float g_att[(size_t)Bb * Nn * Cc];   // attn_out before final proj
__device__ float g_probs_fb[(size_t)Bb * Hh * Nn * Mm]; // fallback if probs not in d_out

// ---------------------------------------------------------------------------
// Generic 1024-K GEMM body: Y[R,1024] = X[R,1024] @ W[1024,1024] + bias
// BM=BN=128, BK=16, 256 threads, 8x8 microtile.
// Optional epilogue: per-column differential-attention weight folded into Q.
// ---------------------------------------------------------------------------
__device__ __forceinline__ void gemm1024_body(
    const float* __restrict__ X, const float* __restrict__ W,
    const float* __restrict__ bias, float* __restrict__ Y,
    const float* __restrict__ lambda_log, bool qweight)
{
    __shared__ float As[16][132];  // transposed X tile [k][m], padded
    __shared__ float Bs[16][132];  // W tile [k][n], padded

    const int tid = threadIdx.x;
    const int tx = tid & 15, ty = tid >> 4;
    const int row0 = blockIdx.y * 128, col0 = blockIdx.x * 128;

    float acc[8][8];
#pragma unroll
    for (int i = 0; i < 8; ++i)
#pragma unroll
        for (int j = 0; j < 8; ++j) acc[i][j] = 0.f;

    for (int k0 = 0; k0 < Cc; k0 += 16) {
#pragma unroll
        for (int l = 0; l < 2; ++l) {
            int idx = tid + l * 256;
            int r  = idx >> 2, c4 = (idx & 3) << 2;
            float4 a = *reinterpret_cast<const float4*>(
                &X[(size_t)(row0 + r) * Cc + k0 + c4]);
            As[c4 + 0][r] = a.x; As[c4 + 1][r] = a.y;
            As[c4 + 2][r] = a.z; As[c4 + 3][r] = a.w;
            int kr = idx >> 5, cc = (idx & 31) << 2;
            *reinterpret_cast<float4*>(&Bs[kr][cc]) =
                *reinterpret_cast<const float4*>(
                    &W[(size_t)(k0 + kr) * Cc + col0 + cc]);
        }
        __syncthreads();
#pragma unroll
        for (int kk = 0; kk < 16; ++kk) {
            float a[8], b[8];
            *reinterpret_cast<float4*>(&a[0]) = *reinterpret_cast<float4*>(&As[kk][ty * 8]);
            *reinterpret_cast<float4*>(&a[4]) = *reinterpret_cast<float4*>(&As[kk][ty * 8 + 4]);
            *reinterpret_cast<float4*>(&b[0]) = *reinterpret_cast<float4*>(&Bs[kk][tx * 8]);
            *reinterpret_cast<float4*>(&b[4]) = *reinterpret_cast<float4*>(&Bs[kk][tx * 8 + 4]);
#pragma unroll
            for (int i = 0; i < 8; ++i)
#pragma unroll
                for (int j = 0; j < 8; ++j) acc[i][j] += a[i] * b[j];
        }
        __syncthreads();
    }

    // Epilogue: bias + optional differential-attention signal weight.
    // w[h,s] = (s even ? +1 : -exp(lambda_log[h][s/2])) * (SD^-0.5 / P)
    float bs[8], wt[8];
#pragma unroll
    for (int j = 0; j < 8; ++j) {
        int col = col0 + tx * 8 + j;
        bs[j] = bias[col];
        float w = 1.f;
        if (qweight) {
            int h = col >> 6;          // / HDd
            int s = (col & 63) >> 3;   // / SDd
            int p = s >> 1;
            float lam = expf(lambda_log[h * Pp + p]);
            const float base = 0.0883883476483184405f; // (1/sqrt(8)) / 4
            w = (s & 1) ? (-lam * base) : base;
        }
        wt[j] = w;
    }
#pragma unroll
    for (int i = 0; i < 8; ++i) {
        int row = row0 + ty * 8 + i;
#pragma unroll
        for (int jj = 0; jj < 8; jj += 4) {
            float4 o;
            o.x = (acc[i][jj + 0] + bs[jj + 0]) * wt[jj + 0];
            o.y = (acc[i][jj + 1] + bs[jj + 1]) * wt[jj + 1];
            o.z = (acc[i][jj + 2] + bs[jj + 2]) * wt[jj + 2];
            o.w = (acc[i][jj + 3] + bs[jj + 3]) * wt[jj + 3];
            *reinterpret_cast<float4*>(
                &Y[(size_t)row * Cc + col0 + tx * 8 + jj]) = o;
        }
    }
}

// Fused QKV projections: blockIdx.z selects which projection. Q gets the
// lambda/scale weighting folded into its epilogue.
__global__ void __launch_bounds__(256) qkv_gemm(
    const float* __restrict__ Xq, const float* __restrict__ Xk, const float* __restrict__ Xv,
    const float* __restrict__ Wq, const float* __restrict__ Wk, const float* __restrict__ Wv,
    const float* __restrict__ bq, const float* __restrict__ bk, const float* __restrict__ bv,
    const float* __restrict__ lambda_log)
{
    int z = blockIdx.z;
    if (z == 0)      gemm1024_body(Xq, Wq, bq, g_q, lambda_log, true);
    else if (z == 1) gemm1024_body(Xk, Wk, bk, g_k, nullptr, false);
    else             gemm1024_body(Xv, Wv, bv, g_v, nullptr, false);
}

__global__ void __launch_bounds__(256) out_gemm(
    const float* __restrict__ Wo, const float* __restrict__ bo, float* __restrict__ Y)
{
    gemm1024_body(g_att, Wo, bo, Y, nullptr, false);
}

// ---------------------------------------------------------------------------
// Scores: per (b,h), logits[n,m] = q'(n)·k(m) over the 64-dim head.
// 64x64 output tile per block; raw logits written into the probs output region.
// ---------------------------------------------------------------------------
__global__ void __launch_bounds__(256) scores_kernel(float* __restrict__ probs)
{
    const int bh = blockIdx.z;
    const int b = bh >> 4, h = bh & 15;
    const int n0 = blockIdx.y * 64, m0 = blockIdx.x * 64;

    __shared__ float Qs[64][68];  // [d][n] transposed
    __shared__ float Ks[64][68];  // [d][m] transposed

    const int tid = threadIdx.x;
    const int tx = tid & 15, ty = tid >> 4;

    const float* qbase = g_q + (size_t)(b * Nn + n0) * Cc + h * HDd;
    const float* kbase = g_k + (size_t)(b * Mm + m0) * Cc + h * HDd;
#pragma unroll
    for (int l = 0; l < 4; ++l) {
        int idx = tid + l * 256;
        int r = idx >> 4, c4 = (idx & 15) << 2;
        float4 qv = *reinterpret_cast<const float4*>(&qbase[(size_t)r * Cc + c4]);
        Qs[c4 + 0][r] = qv.x; Qs[c4 + 1][r] = qv.y;
        Qs[c4 + 2][r] = qv.z; Qs[c4 + 3][r] = qv.w;
        float4 kv = *reinterpret_cast<const float4*>(&kbase[(size_t)r * Cc + c4]);
        Ks[c4 + 0][r] = kv.x; Ks[c4 + 1][r] = kv.y;
        Ks[c4 + 2][r] = kv.z; Ks[c4 + 3][r] = kv.w;
    }
    __syncthreads();

    float acc[4][4] = {};
#pragma unroll
    for (int kk = 0; kk < 64; ++kk) {
        float a[4], bv[4];
        *reinterpret_cast<float4*>(a)  = *reinterpret_cast<float4*>(&Qs[kk][ty * 4]);
        *reinterpret_cast<float4*>(bv) = *reinterpret_cast<float4*>(&Ks[kk][tx * 4]);
#pragma unroll
        for (int i = 0; i < 4; ++i)
#pragma unroll
            for (int j = 0; j < 4; ++j) acc[i][j] += a[i] * bv[j];
    }

    float* obase = probs + ((size_t)(b * Hh + h) * Nn + n0) * Mm + m0;
#pragma unroll
    for (int i = 0; i < 4; ++i) {
        *reinterpret_cast<float4*>(&obase[(size_t)(ty * 4 + i) * Mm + tx * 4]) =
            make_float4(acc[i][0], acc[i][1], acc[i][2], acc[i][3]);
    }
}

// ---------------------------------------------------------------------------
// Softmax over last axis, in place. One block per (b,h,n) row; M=1024 floats.
// ---------------------------------------------------------------------------
__global__ void __launch_bounds__(256) softmax_kernel(float* __restrict__ probs)
{
    __shared__ float redm[8], reds[8];
    const size_t row = blockIdx.x;
    float* p = probs + row * Mm;
    const int tid = threadIdx.x;

    float4 v = reinterpret_cast<float4*>(p)[tid];
    float mx = fmaxf(fmaxf(v.x, v.y), fmaxf(v.z, v.w));
#pragma unroll
    for (int o = 16; o > 0; o >>= 1) mx = fmaxf(mx, __shfl_xor_sync(0xffffffffu, mx, o));
    if ((tid & 31) == 0) redm[tid >> 5] = mx;
    __syncthreads();
    if (tid < 32) {
        float t = (tid < 8) ? redm[tid] : -3.4e38f;
#pragma unroll
        for (int o = 4; o > 0; o >>= 1) t = fmaxf(t, __shfl_xor_sync(0xffffffffu, t, o));
        if (tid == 0) redm[0] = t;
    }
    __syncthreads();
    mx = redm[0];

    float e0 = __expf(v.x - mx), e1 = __expf(v.y - mx);
    float e2 = __expf(v.z - mx), e3 = __expf(v.w - mx);
    float s = e0 + e1 + e2 + e3;
#pragma unroll
    for (int o = 16; o > 0; o >>= 1) s += __shfl_xor_sync(0xffffffffu, s, o);
    if ((tid & 31) == 0) reds[tid >> 5] = s;
    __syncthreads();
    if (tid < 32) {
        float t = (tid < 8) ? reds[tid] : 0.f;
#pragma unroll
        for (int o = 4; o > 0; o >>= 1) t += __shfl_xor_sync(0xffffffffu, t, o);
        if (tid == 0) reds[0] = t;
    }
    __syncthreads();
    float inv = __frcp_rn(reds[0]);
    reinterpret_cast<float4*>(p)[tid] = make_float4(e0 * inv, e1 * inv, e2 * inv, e3 * inv);
}

// ---------------------------------------------------------------------------
// PV: attn_out[n, d] = sum_m probs[n,m] * v[m,d] per (b,h). 64-row block,
// full 64-dim head, looping M in 64-chunks.
// ---------------------------------------------------------------------------
__global__ void __launch_bounds__(256) pv_kernel(const float* __restrict__ probs)
{
    const int bh = blockIdx.y;
    const int b = bh >> 4, h = bh & 15;
    const int n0 = blockIdx.x * 64;

    __shared__ float Ps[64][68];  // [m][n] transposed
    __shared__ float Vs[64][68];  // [m][d]

    const int tid = threadIdx.x;
    const int tx = tid & 15, ty = tid >> 4;
    float acc[4][4] = {};

    const float* pbase = probs + ((size_t)(b * Hh + h) * Nn + n0) * Mm;
    const float* vbase = g_v + (size_t)b * Mm * Cc + h * HDd;

    for (int m0 = 0; m0 < Mm; m0 += 64) {
#pragma unroll
        for (int l = 0; l < 4; ++l) {
            int idx = tid + l * 256;
            int r = idx >> 4, c4 = (idx & 15) << 2;
            float4 pv = *reinterpret_cast<const float4*>(&pbase[(size_t)r * Mm + m0 + c4]);
            Ps[c4 + 0][r] = pv.x; Ps[c4 + 1][r] = pv.y;
            Ps[c4 + 2][r] = pv.z; Ps[c4 + 3][r] = pv.w;
            *reinterpret_cast<float4*>(&Vs[r][c4]) =
                *reinterpret_cast<const float4*>(&vbase[(size_t)(m0 + r) * Cc + c4]);
        }
        __syncthreads();
#pragma unroll
        for (int mm = 0; mm < 64; ++mm) {
            float a[4], bv[4];
            *reinterpret_cast<float4*>(a)  = *reinterpret_cast<float4*>(&Ps[mm][ty * 4]);
            *reinterpret_cast<float4*>(bv) = *reinterpret_cast<float4*>(&Vs[mm][tx * 4]);
#pragma unroll
            for (int i = 0; i < 4; ++i)
#pragma unroll
                for (int j = 0; j < 4; ++j) acc[i][j] += a[i] * bv[j];
        }
        __syncthreads();
    }

    float* obase = g_att + (size_t)(b * Nn + n0) * Cc + h * HDd;
#pragma unroll
    for (int i = 0; i < 4; ++i) {
        *reinterpret_cast<float4*>(&obase[(size_t)(ty * 4 + i) * Cc + tx * 4]) =
            make_float4(acc[i][0], acc[i][1], acc[i][2], acc[i][3]);
    }
}

// ---------------------------------------------------------------------------
extern "C" void kernel_launch(void* const* d_in, const int* in_sizes, int n_in,
                              void* d_out, int out_size)
{
    const float* query      = (const float*)d_in[0];
    const float* key_       = (const float*)d_in[1];
    const float* value      = (const float*)d_in[2];
    const float* Wq         = (const float*)d_in[3];
    const float* bq         = (const float*)d_in[4];
    const float* Wk         = (const float*)d_in[5];
    const float* bk         = (const float*)d_in[6];
    const float* Wv         = (const float*)d_in[7];
    const float* bv         = (const float*)d_in[8];
    const float* Wo         = (const float*)d_in[9];
    const float* bo         = (const float*)d_in[10];
    const float* lambda_log = (const float*)d_in[11];

    float* out = (float*)d_out;
    const long long y_elems = (long long)Bb * Nn * Cc;           // 2,097,152
    const long long p_elems = (long long)Bb * Hh * Nn * Mm;      // 33,554,432

    float* out_p;
    if ((long long)out_size >= y_elems + p_elems) {
        out_p = out + y_elems;   // [output | attn_probs] layout
    } else {
        void* sym = nullptr;
        cudaGetSymbolAddress(&sym, g_probs_fb);
        out_p = (float*)sym;     // probs not part of output: keep internal
    }

    qkv_gemm<<<dim3(8, 16, 3), 256>>>(query, key_, value,
                                      Wq, Wk, Wv, bq, bk, bv, lambda_log);
    scores_kernel<<<dim3(16, 16, 32), 256>>>(out_p);
    softmax_kernel<<<dim3(32768, 1, 1), 256>>>(out_p);
    pv_kernel<<<dim3(16, 32), 256>>>(out_p);
    out_gemm<<<dim3(8, 16), 256>>>(Wo, bo, out);
}

// round 3
// speedup vs baseline: 2.8558x; 2.8558x over previous
#include <cuda_runtime.h>
#include <math.h>
#include <stdint.h>

// Problem constants
#define Bb 2
#define Nn 1024
#define Mm 1024
#define Cc 1024
#define Hh 16
#define Pp 4
#define HDd 64

// ---------------------------------------------------------------------------
// Scratch (device globals — no allocation allowed anywhere)
// ---------------------------------------------------------------------------
__device__ float g_xq[(size_t)Bb * Nn * Cc];   // tf32-rounded inputs
__device__ float g_xk[(size_t)Bb * Mm * Cc];
__device__ float g_xv[(size_t)Bb * Mm * Cc];
__device__ float g_wq[(size_t)Cc * Cc];
__device__ float g_wk[(size_t)Cc * Cc];
__device__ float g_wv[(size_t)Cc * Cc];
__device__ float g_wo[(size_t)Cc * Cc];
__device__ float g_q[(size_t)Bb * Nn * Cc];    // projections (tf32-rounded)
__device__ float g_k[(size_t)Bb * Mm * Cc];
__device__ float g_v[(size_t)Bb * Mm * Cc];
__device__ float g_att[(size_t)Bb * Nn * Cc];  // attn_out (tf32-rounded)
__device__ float g_probs_fb[(size_t)Bb * Hh * Nn * Mm];

// ---------------------------------------------------------------------------
// Helpers
// ---------------------------------------------------------------------------
__device__ __forceinline__ float tf32r(float x) {
    // NOTE: destination of cvt.*.tf32.f32 must be a .b32 register (PTX ISA);
    // "=f" here is a ptxas error. Use "=r" like CUTLASS's float_to_tf32.
    uint32_t y;
    asm("cvt.rna.tf32.f32 %0, %1;" : "=r"(y) : "f"(x));
    return __uint_as_float(y);
}

__device__ __forceinline__ void mma8(float* c, const uint32_t* a, const uint32_t* b) {
    asm volatile(
        "mma.sync.aligned.m16n8k8.row.col.f32.tf32.tf32.f32 "
        "{%0,%1,%2,%3}, {%4,%5,%6,%7}, {%8,%9}, {%0,%1,%2,%3};\n"
        : "+f"(c[0]), "+f"(c[1]), "+f"(c[2]), "+f"(c[3])
        : "r"(a[0]), "r"(a[1]), "r"(a[2]), "r"(a[3]), "r"(b[0]), "r"(b[1]));
}

__device__ __forceinline__ void cp16(void* smem, const void* g) {
    uint32_t s = (uint32_t)__cvta_generic_to_shared(smem);
    asm volatile("cp.async.ca.shared.global [%0], [%1], 16;\n" :: "r"(s), "l"(g));
}
#define CP_COMMIT() asm volatile("cp.async.commit_group;\n")
#define CP_WAIT(n)  asm volatile("cp.async.wait_group %0;\n" :: "n"(n))

__device__ __forceinline__ uint32_t fu(float x) { return __float_as_uint(x); }

// ---------------------------------------------------------------------------
// prep: round 7 input tensors to tf32 (so mma truncation is exact / unbiased)
// grid (2048, 7), block 256, float4 per thread
// ---------------------------------------------------------------------------
__global__ void __launch_bounds__(256) prep_round(
    const float* __restrict__ q, const float* __restrict__ k, const float* __restrict__ v,
    const float* __restrict__ wq, const float* __restrict__ wk,
    const float* __restrict__ wv, const float* __restrict__ wo)
{
    int t = blockIdx.x * 256 + threadIdx.x;
    const float* src; float* dst; int n4;
    switch (blockIdx.y) {
        case 0: src = q;  dst = g_xq; n4 = 524288; break;
        case 1: src = k;  dst = g_xk; n4 = 524288; break;
        case 2: src = v;  dst = g_xv; n4 = 524288; break;
        case 3: src = wq; dst = g_wq; n4 = 262144; break;
        case 4: src = wk; dst = g_wk; n4 = 262144; break;
        case 5: src = wv; dst = g_wv; n4 = 262144; break;
        default: src = wo; dst = g_wo; n4 = 262144; break;
    }
    if (t >= n4) return;
    float4 a = reinterpret_cast<const float4*>(src)[t];
    a.x = tf32r(a.x); a.y = tf32r(a.y); a.z = tf32r(a.z); a.w = tf32r(a.w);
    reinterpret_cast<float4*>(dst)[t] = a;
}

// ---------------------------------------------------------------------------
// Projection GEMM: Y[2048,1024] = X @ W + b, tf32 mma, 128x128 tile, BK=16,
// cp.async double-buffered. Optional q-weight epilogue, optional tf32 rounding.
// ---------------------------------------------------------------------------
__device__ __forceinline__ void proj_body(
    const float* __restrict__ X, const float* __restrict__ W,
    const float* __restrict__ bias, float* __restrict__ Y,
    const float* __restrict__ lambda_log, bool qweight, bool round_out)
{
    __shared__ float As[2][128][20];   // [m][k], pad 20 (conflict-free frags)
    __shared__ float Bs[2][16][136];   // [k][n], pad 136

    const int tid = threadIdx.x;
    const int wid = tid >> 5, lane = tid & 31;
    const int wr = wid >> 2, wc = wid & 3;     // 2x4 warp grid -> 64x32 / warp
    const int grp = lane >> 2, tig = lane & 3;
    const int row0 = blockIdx.y * 128, col0 = blockIdx.x * 128;

    float acc[4][4][4];
#pragma unroll
    for (int i = 0; i < 4; ++i)
#pragma unroll
        for (int j = 0; j < 4; ++j)
#pragma unroll
            for (int r = 0; r < 4; ++r) acc[i][j][r] = 0.f;

    // stage 0 loads
    {
        const int k0 = 0;
#pragma unroll
        for (int l = 0; l < 2; ++l) {
            int idx = tid + l * 256;
            int r = idx >> 2, c4 = (idx & 3) << 2;
            cp16(&As[0][r][c4], &X[(size_t)(row0 + r) * Cc + k0 + c4]);
            int kr = idx >> 5, cc = (idx & 31) << 2;
            cp16(&Bs[0][kr][cc], &W[(size_t)(k0 + kr) * Cc + col0 + cc]);
        }
        CP_COMMIT();
    }

    for (int ko = 0; ko < 64; ++ko) {
        const int buf = ko & 1;
        if (ko + 1 < 64) {
            const int k0 = (ko + 1) * 16, nb = buf ^ 1;
#pragma unroll
            for (int l = 0; l < 2; ++l) {
                int idx = tid + l * 256;
                int r = idx >> 2, c4 = (idx & 3) << 2;
                cp16(&As[nb][r][c4], &X[(size_t)(row0 + r) * Cc + k0 + c4]);
                int kr = idx >> 5, cc = (idx & 31) << 2;
                cp16(&Bs[nb][kr][cc], &W[(size_t)(k0 + kr) * Cc + col0 + cc]);
            }
            CP_COMMIT();
            CP_WAIT(1);
        } else {
            CP_WAIT(0);
        }
        __syncthreads();

#pragma unroll
        for (int ks = 0; ks < 2; ++ks) {
            const int kk = ks * 8;
            uint32_t af[4][4], bf[4][2];
#pragma unroll
            for (int mt = 0; mt < 4; ++mt) {
                int row = wr * 64 + mt * 16 + grp;
                af[mt][0] = fu(As[buf][row][kk + tig]);
                af[mt][1] = fu(As[buf][row + 8][kk + tig]);
                af[mt][2] = fu(As[buf][row][kk + tig + 4]);
                af[mt][3] = fu(As[buf][row + 8][kk + tig + 4]);
            }
#pragma unroll
            for (int nt = 0; nt < 4; ++nt) {
                int col = wc * 32 + nt * 8 + grp;
                bf[nt][0] = fu(Bs[buf][kk + tig][col]);
                bf[nt][1] = fu(Bs[buf][kk + tig + 4][col]);
            }
#pragma unroll
            for (int mt = 0; mt < 4; ++mt)
#pragma unroll
                for (int nt = 0; nt < 4; ++nt)
                    mma8(acc[mt][nt], af[mt], bf[nt]);
        }
        __syncthreads();
    }

    // epilogue
    const float base = 0.0883883476483184405f; // (1/sqrt(8)) / 4
#pragma unroll
    for (int nt = 0; nt < 4; ++nt) {
        int col = col0 + wc * 32 + nt * 8 + 2 * tig;
        float b0 = bias[col], b1 = bias[col + 1];
        float w0 = 1.f, w1 = 1.f;
        if (qweight) {
            int h = col >> 6, s = (col & 63) >> 3, p = s >> 1;
            float lam = expf(lambda_log[h * Pp + p]);
            w0 = (s & 1) ? (-lam * base) : base;
            // col+1 shares the same 8-wide signal block (2*tig+1 < 8)
            w1 = w0;
        }
#pragma unroll
        for (int mt = 0; mt < 4; ++mt) {
            int row = row0 + wr * 64 + mt * 16 + grp;
            float o0 = (acc[mt][nt][0] + b0) * w0;
            float o1 = (acc[mt][nt][1] + b1) * w1;
            float o2 = (acc[mt][nt][2] + b0) * w0;
            float o3 = (acc[mt][nt][3] + b1) * w1;
            if (round_out) { o0 = tf32r(o0); o1 = tf32r(o1); o2 = tf32r(o2); o3 = tf32r(o3); }
            *reinterpret_cast<float2*>(&Y[(size_t)row * Cc + col]) = make_float2(o0, o1);
            *reinterpret_cast<float2*>(&Y[(size_t)(row + 8) * Cc + col]) = make_float2(o2, o3);
        }
    }
}

__global__ void __launch_bounds__(256) qkv_gemm(
    const float* __restrict__ bq, const float* __restrict__ bk, const float* __restrict__ bv,
    const float* __restrict__ lambda_log)
{
    int z = blockIdx.z;
    if (z == 0)      proj_body(g_xq, g_wq, bq, g_q, lambda_log, true, true);
    else if (z == 1) proj_body(g_xk, g_wk, bk, g_k, nullptr, false, true);
    else             proj_body(g_xv, g_wv, bv, g_v, nullptr, false, true);
}

__global__ void __launch_bounds__(256) out_gemm(
    const float* __restrict__ bo, float* __restrict__ Y)
{
    proj_body(g_att, g_wo, bo, Y, nullptr, false, false);
}

// ---------------------------------------------------------------------------
// Scores: per (b,h) logits[n,m] = q.k over 64 dims, tf32 mma, 128x128 tile.
// K=64 processed as 2 chunks of 32 (sync loads; latency hidden across blocks).
// ---------------------------------------------------------------------------
__global__ void __launch_bounds__(256) scores_kernel(float* __restrict__ probs)
{
    const int bh = blockIdx.z;
    const int b = bh >> 4, h = bh & 15;
    const int n0 = blockIdx.y * 128, m0 = blockIdx.x * 128;

    __shared__ float Qs[128][36];  // [n][d-chunk], pad 36
    __shared__ float Ks[128][36];  // [m][d-chunk]

    const int tid = threadIdx.x;
    const int wid = tid >> 5, lane = tid & 31;
    const int wr = wid >> 2, wc = wid & 3;
    const int grp = lane >> 2, tig = lane & 3;

    float acc[4][4][4];
#pragma unroll
    for (int i = 0; i < 4; ++i)
#pragma unroll
        for (int j = 0; j < 4; ++j)
#pragma unroll
            for (int r = 0; r < 4; ++r) acc[i][j][r] = 0.f;

    const float* qb = g_q + (size_t)(b * Nn + n0) * Cc + h * HDd;
    const float* kb = g_k + (size_t)(b * Mm + m0) * Cc + h * HDd;

    for (int kc = 0; kc < 2; ++kc) {
        const int d0 = kc * 32;
#pragma unroll
        for (int l = 0; l < 4; ++l) {
            int idx = tid + l * 256;
            int r = idx >> 3, c4 = (idx & 7) << 2;
            *reinterpret_cast<float4*>(&Qs[r][c4]) =
                *reinterpret_cast<const float4*>(&qb[(size_t)r * Cc + d0 + c4]);
            *reinterpret_cast<float4*>(&Ks[r][c4]) =
                *reinterpret_cast<const float4*>(&kb[(size_t)r * Cc + d0 + c4]);
        }
        __syncthreads();

#pragma unroll
        for (int ks = 0; ks < 4; ++ks) {
            const int kk = ks * 8;
            uint32_t af[4][4], bf[4][2];
#pragma unroll
            for (int mt = 0; mt < 4; ++mt) {
                int row = wr * 64 + mt * 16 + grp;
                af[mt][0] = fu(Qs[row][kk + tig]);
                af[mt][1] = fu(Qs[row + 8][kk + tig]);
                af[mt][2] = fu(Qs[row][kk + tig + 4]);
                af[mt][3] = fu(Qs[row + 8][kk + tig + 4]);
            }
#pragma unroll
            for (int nt = 0; nt < 4; ++nt) {
                int col = wc * 32 + nt * 8 + grp;
                bf[nt][0] = fu(Ks[col][kk + tig]);
                bf[nt][1] = fu(Ks[col][kk + tig + 4]);
            }
#pragma unroll
            for (int mt = 0; mt < 4; ++mt)
#pragma unroll
                for (int nt = 0; nt < 4; ++nt)
                    mma8(acc[mt][nt], af[mt], bf[nt]);
        }
        __syncthreads();
    }

    float* ob = probs + ((size_t)bh * Nn + n0) * Mm + m0;
#pragma unroll
    for (int mt = 0; mt < 4; ++mt) {
        int row = wr * 64 + mt * 16 + grp;
#pragma unroll
        for (int nt = 0; nt < 4; ++nt) {
            int col = wc * 32 + nt * 8 + 2 * tig;
            *reinterpret_cast<float2*>(&ob[(size_t)row * Mm + col]) =
                make_float2(acc[mt][nt][0], acc[mt][nt][1]);
            *reinterpret_cast<float2*>(&ob[(size_t)(row + 8) * Mm + col]) =
                make_float2(acc[mt][nt][2], acc[mt][nt][3]);
        }
    }
}

// ---------------------------------------------------------------------------
// Softmax in place over last axis; stores tf32-rounded probs (pv mma input).
// ---------------------------------------------------------------------------
__global__ void __launch_bounds__(256) softmax_kernel(float* __restrict__ probs)
{
    __shared__ float redm[8], reds[8];
    float* p = probs + (size_t)blockIdx.x * Mm;
    const int tid = threadIdx.x;

    float4 v = reinterpret_cast<float4*>(p)[tid];
    float mx = fmaxf(fmaxf(v.x, v.y), fmaxf(v.z, v.w));
#pragma unroll
    for (int o = 16; o > 0; o >>= 1) mx = fmaxf(mx, __shfl_xor_sync(0xffffffffu, mx, o));
    if ((tid & 31) == 0) redm[tid >> 5] = mx;
    __syncthreads();
    if (tid < 32) {
        float t = (tid < 8) ? redm[tid] : -3.4e38f;
#pragma unroll
        for (int o = 4; o > 0; o >>= 1) t = fmaxf(t, __shfl_xor_sync(0xffffffffu, t, o));
        if (tid == 0) redm[0] = t;
    }
    __syncthreads();
    mx = redm[0];

    float e0 = __expf(v.x - mx), e1 = __expf(v.y - mx);
    float e2 = __expf(v.z - mx), e3 = __expf(v.w - mx);
    float s = e0 + e1 + e2 + e3;
#pragma unroll
    for (int o = 16; o > 0; o >>= 1) s += __shfl_xor_sync(0xffffffffu, s, o);
    if ((tid & 31) == 0) reds[tid >> 5] = s;
    __syncthreads();
    if (tid < 32) {
        float t = (tid < 8) ? reds[tid] : 0.f;
#pragma unroll
        for (int o = 4; o > 0; o >>= 1) t += __shfl_xor_sync(0xffffffffu, t, o);
        if (tid == 0) reds[0] = t;
    }
    __syncthreads();
    float inv = __frcp_rn(reds[0]);
    reinterpret_cast<float4*>(p)[tid] =
        make_float4(tf32r(e0 * inv), tf32r(e1 * inv), tf32r(e2 * inv), tf32r(e3 * inv));
}

// ---------------------------------------------------------------------------
// PV: attn_out[n,d] = sum_m P[n,m] V[m,d] per (b,h). tf32 mma, 128x64 tile,
// BK=16, cp.async double-buffered. Output tf32-rounded into g_att.
// ---------------------------------------------------------------------------
__global__ void __launch_bounds__(256) pv_kernel(const float* __restrict__ probs)
{
    const int bh = blockIdx.y;
    const int b = bh >> 4, h = bh & 15;
    const int n0 = blockIdx.x * 128;

    __shared__ float Ps[2][128][20];  // [n][k], pad 20
    __shared__ float Vs[2][16][72];   // [m][d], pad 72

    const int tid = threadIdx.x;
    const int wid = tid >> 5, lane = tid & 31;
    const int wr = wid >> 1, wc = wid & 1;   // 4x2 warp grid -> 32n x 32d / warp
    const int grp = lane >> 2, tig = lane & 3;

    float acc[2][4][4];
#pragma unroll
    for (int i = 0; i < 2; ++i)
#pragma unroll
        for (int j = 0; j < 4; ++j)
#pragma unroll
            for (int r = 0; r < 4; ++r) acc[i][j][r] = 0.f;

    const float* pb = probs + ((size_t)bh * Nn + n0) * Mm;
    const float* vb = g_v + (size_t)b * Mm * Cc + h * HDd;

    // stage 0
    {
#pragma unroll
        for (int l = 0; l < 2; ++l) {
            int idx = tid + l * 256;
            int r = idx >> 2, c4 = (idx & 3) << 2;
            cp16(&Ps[0][r][c4], &pb[(size_t)r * Mm + c4]);
        }
        int vr = tid >> 4, vc4 = (tid & 15) << 2;
        cp16(&Vs[0][vr][vc4], &vb[(size_t)vr * Cc + vc4]);
        CP_COMMIT();
    }

    for (int ko = 0; ko < 64; ++ko) {
        const int buf = ko & 1;
        if (ko + 1 < 64) {
            const int k0 = (ko + 1) * 16, nb = buf ^ 1;
#pragma unroll
            for (int l = 0; l < 2; ++l) {
                int idx = tid + l * 256;
                int r = idx >> 2, c4 = (idx & 3) << 2;
                cp16(&Ps[nb][r][c4], &pb[(size_t)r * Mm + k0 + c4]);
            }
            int vr = tid >> 4, vc4 = (tid & 15) << 2;
            cp16(&Vs[nb][vr][vc4], &vb[(size_t)(k0 + vr) * Cc + vc4]);
            CP_COMMIT();
            CP_WAIT(1);
        } else {
            CP_WAIT(0);
        }
        __syncthreads();

#pragma unroll
        for (int ks = 0; ks < 2; ++ks) {
            const int kk = ks * 8;
            uint32_t af[2][4], bf[4][2];
#pragma unroll
            for (int mt = 0; mt < 2; ++mt) {
                int row = wr * 32 + mt * 16 + grp;
                af[mt][0] = fu(Ps[buf][row][kk + tig]);
                af[mt][1] = fu(Ps[buf][row + 8][kk + tig]);
                af[mt][2] = fu(Ps[buf][row][kk + tig + 4]);
                af[mt][3] = fu(Ps[buf][row + 8][kk + tig + 4]);
            }
#pragma unroll
            for (int nt = 0; nt < 4; ++nt) {
                int col = wc * 32 + nt * 8 + grp;
                bf[nt][0] = fu(Vs[buf][kk + tig][col]);
                bf[nt][1] = fu(Vs[buf][kk + tig + 4][col]);
            }
#pragma unroll
            for (int mt = 0; mt < 2; ++mt)
#pragma unroll
                for (int nt = 0; nt < 4; ++nt)
                    mma8(acc[mt][nt], af[mt], bf[nt]);
        }
        __syncthreads();
    }

    float* ob = g_att + (size_t)(b * Nn + n0) * Cc + h * HDd;
#pragma unroll
    for (int mt = 0; mt < 2; ++mt) {
        int row = wr * 32 + mt * 16 + grp;
#pragma unroll
        for (int nt = 0; nt < 4; ++nt) {
            int col = wc * 32 + nt * 8 + 2 * tig;
            *reinterpret_cast<float2*>(&ob[(size_t)row * Cc + col]) =
                make_float2(tf32r(acc[mt][nt][0]), tf32r(acc[mt][nt][1]));
            *reinterpret_cast<float2*>(&ob[(size_t)(row + 8) * Cc + col]) =
                make_float2(tf32r(acc[mt][nt][2]), tf32r(acc[mt][nt][3]));
        }
    }
}

// ---------------------------------------------------------------------------
extern "C" void kernel_launch(void* const* d_in, const int* in_sizes, int n_in,
                              void* d_out, int out_size)
{
    const float* query      = (const float*)d_in[0];
    const float* key_       = (const float*)d_in[1];
    const float* value      = (const float*)d_in[2];
    const float* bq         = (const float*)d_in[4];
    const float* bk         = (const float*)d_in[6];
    const float* bv         = (const float*)d_in[8];
    const float* bo         = (const float*)d_in[10];
    const float* lambda_log = (const float*)d_in[11];
    const float* Wq         = (const float*)d_in[3];
    const float* Wk         = (const float*)d_in[5];
    const float* Wv         = (const float*)d_in[7];
    const float* Wo         = (const float*)d_in[9];

    float* out = (float*)d_out;
    const long long y_elems = (long long)Bb * Nn * Cc;
    const long long p_elems = (long long)Bb * Hh * Nn * Mm;

    float* out_p;
    if ((long long)out_size >= y_elems + p_elems) {
        out_p = out + y_elems;
    } else {
        void* sym = nullptr;
        cudaGetSymbolAddress(&sym, g_probs_fb);
        out_p = (float*)sym;
    }

    prep_round<<<dim3(2048, 7), 256>>>(query, key_, value, Wq, Wk, Wv, Wo);
    qkv_gemm<<<dim3(8, 16, 3), 256>>>(bq, bk, bv, lambda_log);
    scores_kernel<<<dim3(8, 8, 32), 256>>>(out_p);
    softmax_kernel<<<dim3(32768, 1, 1), 256>>>(out_p);
    pv_kernel<<<dim3(8, 32), 256>>>(out_p);
    out_gemm<<<dim3(8, 16), 256>>>(bo, out);
}